// round 16
// baseline (speedup 1.0000x reference)
#include <cuda_runtime.h>
#include <cuda_fp16.h>

#define N_NODES 100000
#define N_EDGES 1600000
#define C_IN    128
#define C       64
#define HID3    256
#define SCAN_B  512
#define SCAN_NB 196   // ceil(100000/512)
#define EDGE_BLK ((N_EDGES + 255) / 256)   // 6250

// ---------------- scratch (device globals; no allocation allowed) ----------
__device__ int     g_is64;
__device__ int     g_deg[N_NODES];
__device__ float   g_dinv[N_NODES];
__device__ int     g_rowptr[N_NODES + 1];
__device__ int     g_writepos[N_NODES];
__device__ volatile int g_aggv[SCAN_NB];
__device__ volatile int g_incv[SCAN_NB];
__device__ volatile int g_flag[SCAN_NB];   // 0 none / 1 aggregate / 2 inclusive
__device__ int     g_colsrc[N_EDGES];
__device__ __half2 g_bufA0[N_NODES * 32];  // h_s layer1 (fp16 gather payload)
__device__ __half2 g_bufA1[N_NODES * 32];  // h_s layer2
__device__ float   g_Wc[C * C];            // W3@W4 folded
__device__ float   g_bc[C];                // b3@W4 + b4 folded

// ---------------- packed f32x2 helpers (Blackwell FFMA2) --------------------
__device__ __forceinline__ unsigned long long pk2(float lo, float hi) {
    unsigned long long r;
    asm("mov.b64 %0, {%1, %2};" : "=l"(r) : "f"(lo), "f"(hi));
    return r;
}
__device__ __forceinline__ void ffma2(unsigned long long& acc,
                                      unsigned long long a, unsigned long long b) {
    asm("fma.rn.f32x2 %0, %1, %2, %3;" : "=l"(acc) : "l"(a), "l"(b), "l"(acc));
}
__device__ __forceinline__ float2 upk2(unsigned long long v) {
    float2 f;
    asm("mov.b64 {%0, %1}, %2;" : "=f"(f.x), "=f"(f.y) : "l"(v));
    return f;
}

// ---------------- zero deg + scan flags + dtype probe -----------------------
__global__ void k_zero_probe(const int* __restrict__ ei32) {
    int i = blockIdx.x * blockDim.x + threadIdx.x;
    if (i < N_NODES) g_deg[i] = 0;
    if (i < SCAN_NB) { g_flag[i] = 0; }
    if (i == 0) {
        int all_hi_zero = 1;
        #pragma unroll 1
        for (int j = 0; j < 256; j++)
            if (ei32[2 * j + 1] != 0) { all_hi_zero = 0; break; }
        g_is64 = all_hi_zero;
    }
}

// histogram of dst only
__global__ void k_build(const void* __restrict__ ei) {
    int e = blockIdx.x * blockDim.x + threadIdx.x;
    if (e >= N_EDGES) return;
    int d;
    if (g_is64) d = (int)((const long long*)ei)[N_EDGES + e];
    else        d = ((const int*)ei)[N_EDGES + e];
    if ((unsigned)d >= N_NODES) d = 0;
    atomicAdd(&g_deg[d], 1);
}

// single-pass exclusive scan (decoupled lookback); also emits dinv + writepos
__global__ void k_scan() {
    __shared__ int sh[SCAN_B];
    __shared__ int s_prefix;
    int b = blockIdx.x;
    int t = threadIdx.x;
    int i = b * SCAN_B + t;
    int v = (i < N_NODES) ? g_deg[i] : 0;
    if (i < N_NODES) g_dinv[i] = rsqrtf((float)v + 1.0f);
    sh[t] = v;
    __syncthreads();
    for (int off = 1; off < SCAN_B; off <<= 1) {
        int add = (t >= off) ? sh[t - off] : 0;
        __syncthreads();
        sh[t] += add;
        __syncthreads();
    }
    if (t == 0) {
        int total = sh[SCAN_B - 1];
        if (b == 0) {
            g_incv[0] = total;
            __threadfence();
            g_flag[0] = 2;
            s_prefix = 0;
        } else {
            g_aggv[b] = total;
            __threadfence();
            g_flag[b] = 1;
            int prefix = 0, p = b - 1;
            while (true) {
                int f;
                while ((f = g_flag[p]) == 0) { }
                if (f == 2) { prefix += g_incv[p]; break; }
                prefix += g_aggv[p];
                p--;
            }
            g_incv[b] = prefix + total;
            __threadfence();
            g_flag[b] = 2;
            s_prefix = prefix;
        }
    }
    __syncthreads();
    int prefix = s_prefix;
    if (i < N_NODES) {
        int r = sh[t] - v + prefix;   // exclusive
        g_rowptr[i]   = r;
        g_writepos[i] = r;
    }
    if (b == SCAN_NB - 1 && t == 0) g_rowptr[N_NODES] = N_EDGES;
}

// blocks [0, EDGE_BLK): CSR column fill.  blocks [EDGE_BLK, EDGE_BLK+65): Wc fold.
__global__ void k_fill_wc(const void* __restrict__ ei,
                          const float* __restrict__ W3, const float* __restrict__ W4,
                          const float* __restrict__ b3, const float* __restrict__ b4) {
    if (blockIdx.x < EDGE_BLK) {
        int e = blockIdx.x * blockDim.x + threadIdx.x;
        if (e >= N_EDGES) return;
        int s, d;
        if (g_is64) {
            const long long* p = (const long long*)ei;
            s = (int)p[e];
            d = (int)p[N_EDGES + e];
        } else {
            const int* p = (const int*)ei;
            s = p[e];
            d = p[N_EDGES + e];
        }
        if ((unsigned)s >= N_NODES || (unsigned)d >= N_NODES) { s = 0; d = 0; }
        int p2 = atomicAdd(&g_writepos[d], 1);
        g_colsrc[p2] = s;
    } else {
        __shared__ float w3row[HID3];
        __shared__ float part[4][C];
        int bid = blockIdx.x - EDGE_BLK;    // 0..64
        int c  = threadIdx.x & 63;
        int jq = threadIdx.x >> 6;          // 0..3
        if (bid < 64) {
            w3row[threadIdx.x] = W3[bid * HID3 + threadIdx.x];
            __syncthreads();
            float acc = 0.0f;
            #pragma unroll 8
            for (int jj = 0; jj < 64; jj++) {
                int j = jq * 64 + jj;
                acc = fmaf(w3row[j], W4[j * C + c], acc);
            }
            part[jq][c] = acc;
            __syncthreads();
            if (jq == 0)
                g_Wc[bid * C + c] = (part[0][c] + part[1][c]) + (part[2][c] + part[3][c]);
        } else {
            float acc = 0.0f;
            #pragma unroll 8
            for (int jj = 0; jj < 64; jj++) {
                int j = jq * 64 + jj;
                acc = fmaf(b3[j], W4[j * C + c], acc);
            }
            part[jq][c] = acc;
            __syncthreads();
            if (jq == 0)
                g_bc[c] = (part[0][c] + part[1][c]) + (part[2][c] + part[3][c]) + b4[c];
        }
    }
}

// ---------------- GEMM core (FFMA2, 128 thr, 32x64 tile) --------------------
// Computes acc2 from Xs/Ws staged in smem. Caller owns fills + epilogue.
__device__ __forceinline__ void gemm_core(const float (*Xs)[64], const float (*Ws)[64],
                                          unsigned long long acc2[4][2],
                                          int rg, int cg) {
    #pragma unroll 16
    for (int kk = 0; kk < 64; kk++) {
        ulonglong2 wp = *(const ulonglong2*)&Ws[kk][cg * 4];
        unsigned long long x0 = pk2(Xs[rg * 4 + 0][kk], Xs[rg * 4 + 0][kk]);
        unsigned long long x1 = pk2(Xs[rg * 4 + 1][kk], Xs[rg * 4 + 1][kk]);
        unsigned long long x2 = pk2(Xs[rg * 4 + 2][kk], Xs[rg * 4 + 2][kk]);
        unsigned long long x3 = pk2(Xs[rg * 4 + 3][kk], Xs[rg * 4 + 3][kk]);
        ffma2(acc2[0][0], x0, wp.x); ffma2(acc2[0][1], x0, wp.y);
        ffma2(acc2[1][0], x1, wp.x); ffma2(acc2[1][1], x1, wp.y);
        ffma2(acc2[2][0], x2, wp.x); ffma2(acc2[2][1], x2, wp.y);
        ffma2(acc2[3][0], x3, wp.x); ffma2(acc2[3][1], x3, wp.y);
    }
}

// ---------------- GEMM1: bufA0 = fp16( (x @ W1) * dinv ) --------------------
__global__ void k_gemm1(const float* __restrict__ X, const float* __restrict__ W) {
    __shared__ float Xs[32][64];
    __shared__ float Ws[64][64];
    int tid = threadIdx.x;
    int cg  = tid & 15;
    int rg  = tid >> 4;
    int row0 = blockIdx.x * 32;

    unsigned long long acc2[4][2] = {};

    for (int k0 = 0; k0 < C_IN; k0 += 64) {
        #pragma unroll
        for (int idx = tid; idx < 32 * 16; idx += 128) {
            int r = idx >> 4, kq = idx & 15;
            *(float4*)&Xs[r][kq * 4] = *(const float4*)&X[(row0 + r) * C_IN + k0 + kq * 4];
        }
        #pragma unroll
        for (int idx = tid; idx < 64 * 16; idx += 128) {
            int kk = idx >> 4, cq = idx & 15;
            *(float4*)&Ws[kk][cq * 4] = *(const float4*)&W[(k0 + kk) * C + cq * 4];
        }
        __syncthreads();
        gemm_core(Xs, Ws, acc2, rg, cg);
        __syncthreads();
    }

    #pragma unroll
    for (int j = 0; j < 4; j++) {
        int r = row0 + rg * 4 + j;
        float s = g_dinv[r];
        float2 p0 = upk2(acc2[j][0]);
        float2 p1 = upk2(acc2[j][1]);
        __half2 h0 = __floats2half2_rn(p0.x * s, p0.y * s);
        __half2 h1 = __floats2half2_rn(p1.x * s, p1.y * s);
        uint2 u;
        u.x = *(const unsigned int*)&h0;
        u.y = *(const unsigned int*)&h1;
        *(uint2*)&g_bufA0[r * 32 + cg * 2] = u;
    }
}

// ---------------- fused agg + GEMM ------------------------------------------
// Phase 1: block aggregates its 32 nodes from Hin (fp16) into Xs (fp32, post
//          relu/bias/dinv).  Phase 2: GEMM on Xs.
// MODE 1: Hin=bufA0, W=W2  -> bufA1 = fp16(acc * dinv)
// MODE 2: Hin=bufA1, W=g_Wc -> acc + bc, fused log_softmax -> Out
template <int MODE>
__global__ void k_agg_gemm(const float* __restrict__ bias, const float* __restrict__ Wext,
                           float* __restrict__ Out) {
    __shared__ float Xs[32][64];
    __shared__ float Ws[64][64];
    const __half2* H = (MODE == 1) ? g_bufA0 : g_bufA1;
    const float*   W = (MODE == 2) ? g_Wc : Wext;

    int tid  = threadIdx.x;
    int warp = tid >> 5;
    int lane = tid & 31;
    int row0 = blockIdx.x * 32;

    // W fill (no dependency on agg)
    #pragma unroll
    for (int idx = tid; idx < 64 * 16; idx += 128) {
        int kk = idx >> 4, cq = idx & 15;
        *(float4*)&Ws[kk][cq * 4] = *(const float4*)&W[kk * C + cq * 4];
    }

    // Phase 1: aggregate 8 nodes per warp
    float2 b = ((const float2*)bias)[lane];
    #pragma unroll 1
    for (int j = 0; j < 8; j++) {
        int n = row0 + warp * 8 + j;
        float2 acc = __half22float2(H[n * 32 + lane]);   // self-loop
        int beg = g_rowptr[n];
        int end = g_rowptr[n + 1];
        int e = beg;
        for (; e + 4 <= end; e += 4) {
            int s0 = g_colsrc[e + 0];
            int s1 = g_colsrc[e + 1];
            int s2 = g_colsrc[e + 2];
            int s3 = g_colsrc[e + 3];
            float2 v0 = __half22float2(H[s0 * 32 + lane]);
            float2 v1 = __half22float2(H[s1 * 32 + lane]);
            float2 v2 = __half22float2(H[s2 * 32 + lane]);
            float2 v3 = __half22float2(H[s3 * 32 + lane]);
            acc.x += (v0.x + v1.x) + (v2.x + v3.x);
            acc.y += (v0.y + v1.y) + (v2.y + v3.y);
        }
        for (; e < end; e++) {
            int s = g_colsrc[e];
            float2 v = __half22float2(H[s * 32 + lane]);
            acc.x += v.x;
            acc.y += v.y;
        }
        float d = g_dinv[n];
        Xs[warp * 8 + j][2 * lane]     = fmaxf(fmaf(acc.x, d, b.x), 0.0f);
        Xs[warp * 8 + j][2 * lane + 1] = fmaxf(fmaf(acc.y, d, b.y), 0.0f);
    }
    __syncthreads();

    // Phase 2: GEMM
    int cg = tid & 15;
    int rg = tid >> 4;
    unsigned long long acc2[4][2] = {};
    gemm_core(Xs, Ws, acc2, rg, cg);

    if (MODE == 1) {
        #pragma unroll
        for (int j = 0; j < 4; j++) {
            int r = row0 + rg * 4 + j;
            float s = g_dinv[r];
            float2 p0 = upk2(acc2[j][0]);
            float2 p1 = upk2(acc2[j][1]);
            __half2 h0 = __floats2half2_rn(p0.x * s, p0.y * s);
            __half2 h1 = __floats2half2_rn(p1.x * s, p1.y * s);
            uint2 u;
            u.x = *(const unsigned int*)&h0;
            u.y = *(const unsigned int*)&h1;
            *(uint2*)&g_bufA1[r * 32 + cg * 2] = u;
        }
    } else {
        __syncthreads();   // Xs reuse below
        #pragma unroll
        for (int j = 0; j < 4; j++) {
            float2 p0 = upk2(acc2[j][0]);
            float2 p1 = upk2(acc2[j][1]);
            float4 o;
            o.x = p0.x + g_bc[cg * 4 + 0];
            o.y = p0.y + g_bc[cg * 4 + 1];
            o.z = p1.x + g_bc[cg * 4 + 2];
            o.w = p1.y + g_bc[cg * 4 + 3];
            *(float4*)&Xs[rg * 4 + j][cg * 4] = o;
        }
        __syncthreads();
        #pragma unroll
        for (int j = 0; j < 8; j++) {
            int r = warp * 8 + j;
            float2 y = ((const float2*)&Xs[r][0])[lane];
            float m = fmaxf(y.x, y.y);
            #pragma unroll
            for (int off = 16; off; off >>= 1)
                m = fmaxf(m, __shfl_xor_sync(0xffffffffu, m, off));
            float se = expf(y.x - m) + expf(y.y - m);
            #pragma unroll
            for (int off = 16; off; off >>= 1)
                se += __shfl_xor_sync(0xffffffffu, se, off);
            float lse = m + logf(se);
            float2 o;
            o.x = y.x - lse;
            o.y = y.y - lse;
            ((float2*)&Out[(row0 + r) * C])[lane] = o;
        }
    }
}

// ---------------- launch ----------------------------------------------------
extern "C" void kernel_launch(void* const* d_in, const int* in_sizes, int n_in,
                              void* d_out, int out_size) {
    const float* x  = (const float*)d_in[0];
    const void*  ei = d_in[1];
    const float* W1 = (const float*)d_in[2];
    const float* b1 = (const float*)d_in[3];
    const float* W2 = (const float*)d_in[4];
    const float* b2 = (const float*)d_in[5];
    const float* W3 = (const float*)d_in[6];
    const float* b3 = (const float*)d_in[7];
    const float* W4 = (const float*)d_in[8];
    const float* b4 = (const float*)d_in[9];
    float* out = (float*)d_out;

    const int NODE_BLK = (N_NODES + 255) / 256;
    const int GEMM_BLK = N_NODES / 32;   // 3125, exact

    k_zero_probe<<<NODE_BLK, 256>>>((const int*)ei);
    k_build<<<EDGE_BLK, 256>>>(ei);
    k_scan<<<SCAN_NB, SCAN_B>>>();
    k_fill_wc<<<EDGE_BLK + 65, 256>>>(ei, W3, W4, b3, b4);

    k_gemm1<<<GEMM_BLK, 128>>>(x, W1);
    k_agg_gemm<1><<<GEMM_BLK, 128>>>(b1, W2, nullptr);
    k_agg_gemm<2><<<GEMM_BLK, 128>>>(b2, nullptr, out);
}

// round 17
// speedup vs baseline: 1.1546x; 1.1546x over previous
#include <cuda_runtime.h>
#include <cuda_fp16.h>

#define N_NODES 100000
#define N_EDGES 1600000
#define C_IN    128
#define C       64
#define HID3    256
#define SCAN_B  512
#define SCAN_NB 196                         // ceil(100000/512)
#define EDGE_BLK  ((N_EDGES + 255) / 256)   // 6250 (exact: 6250*256 = 1.6M)
#define GEMM1_BLK ((N_NODES + 63) / 64)     // 1563

// ---------------- scratch (device globals; no allocation allowed) ----------
__device__ int     g_is64;
__device__ int     g_deg[N_NODES];
__device__ float   g_dinv[N_NODES];
__device__ int     g_rowptr[N_NODES + 1];
__device__ int     g_writepos[N_NODES];
__device__ int     g_blocksums[SCAN_B];
__device__ int     g_colsrc[N_EDGES];
__device__ __half2 g_bufA0[N_NODES * 32];  // h (layer1, UNscaled) fp16
__device__ __half2 g_bufA1[N_NODES * 32];  // h*dinv (layer2, scaled) fp16
__device__ float   g_bufB[N_NODES * C];    // agg outputs (fp32)
__device__ float   g_Wc[C * C];            // W3@W4 folded
__device__ float   g_bc[C];                // b3@W4 + b4 folded

// ---------------- packed f32x2 helpers (Blackwell FFMA2) --------------------
__device__ __forceinline__ unsigned long long pk2(float lo, float hi) {
    unsigned long long r;
    asm("mov.b64 %0, {%1, %2};" : "=l"(r) : "f"(lo), "f"(hi));
    return r;
}
__device__ __forceinline__ void ffma2(unsigned long long& acc,
                                      unsigned long long a, unsigned long long b) {
    asm("fma.rn.f32x2 %0, %1, %2, %3;" : "=l"(acc) : "l"(a), "l"(b), "l"(acc));
}
__device__ __forceinline__ float2 upk2(unsigned long long v) {
    float2 f;
    asm("mov.b64 {%0, %1}, %2;" : "=f"(f.x), "=f"(f.y) : "l"(v));
    return f;
}

// ---------------- GEMM core (FFMA2): rows rg*4..rg*4+3, cols cg*4..cg*4+3 ---
template <typename XS>
__device__ __forceinline__ void gemm_core(const XS& Xs, const float (*Ws)[64],
                                          unsigned long long acc2[4][2],
                                          int rg, int cg) {
    #pragma unroll 16
    for (int kk = 0; kk < 64; kk++) {
        ulonglong2 wp = *(const ulonglong2*)&Ws[kk][cg * 4];
        unsigned long long x0 = pk2(Xs[rg * 4 + 0][kk], Xs[rg * 4 + 0][kk]);
        unsigned long long x1 = pk2(Xs[rg * 4 + 1][kk], Xs[rg * 4 + 1][kk]);
        unsigned long long x2 = pk2(Xs[rg * 4 + 2][kk], Xs[rg * 4 + 2][kk]);
        unsigned long long x3 = pk2(Xs[rg * 4 + 3][kk], Xs[rg * 4 + 3][kk]);
        ffma2(acc2[0][0], x0, wp.x); ffma2(acc2[0][1], x0, wp.y);
        ffma2(acc2[1][0], x1, wp.x); ffma2(acc2[1][1], x1, wp.y);
        ffma2(acc2[2][0], x2, wp.x); ffma2(acc2[2][1], x2, wp.y);
        ffma2(acc2[3][0], x3, wp.x); ffma2(acc2[3][1], x3, wp.y);
    }
}

// ---------------- zero deg + dtype probe ------------------------------------
__global__ void k_zero_probe(const int* __restrict__ ei32) {
    int i = blockIdx.x * blockDim.x + threadIdx.x;
    if (i < N_NODES) g_deg[i] = 0;
    if (i == 0) {
        int all_hi_zero = 1;
        #pragma unroll 1
        for (int j = 0; j < 256; j++)
            if (ei32[2 * j + 1] != 0) { all_hi_zero = 0; break; }
        g_is64 = all_hi_zero;
    }
}

// ---------------- fat kernel: histogram | GEMM1 | Wc fold -------------------
// blocks [0, EDGE_BLK):                     dst histogram
// blocks [EDGE_BLK, EDGE_BLK+GEMM1_BLK):    bufA0 = fp16(x @ W1)   (UNscaled)
// blocks [EDGE_BLK+GEMM1_BLK, +65):         Wc = W3@W4, bc = b3@W4+b4
__global__ void k_fat(const void* __restrict__ ei,
                      const float* __restrict__ X, const float* __restrict__ W1,
                      const float* __restrict__ W3, const float* __restrict__ W4,
                      const float* __restrict__ b3, const float* __restrict__ b4) {
    __shared__ float smem[2 * 64 * 64];     // 32KB, aliased per branch
    int tid = threadIdx.x;

    if (blockIdx.x < EDGE_BLK) {
        int e = blockIdx.x * blockDim.x + tid;
        if (e >= N_EDGES) return;
        int d;
        if (g_is64) d = (int)((const long long*)ei)[N_EDGES + e];
        else        d = ((const int*)ei)[N_EDGES + e];
        if ((unsigned)d >= N_NODES) d = 0;
        atomicAdd(&g_deg[d], 1);
    } else if (blockIdx.x < EDGE_BLK + GEMM1_BLK) {
        // 256-thread GEMM: 64-row tile, thread-tile 4x4 (rg 0..15, cg 0..15)
        float (*Xs)[64] = (float(*)[64])smem;
        float (*Ws)[64] = (float(*)[64])(smem + 64 * 64);
        int row0 = (blockIdx.x - EDGE_BLK) * 64;
        int cg = tid & 15;
        int rg = tid >> 4;
        unsigned long long acc2[4][2] = {};

        for (int k0 = 0; k0 < C_IN; k0 += 64) {
            #pragma unroll
            for (int idx = tid; idx < 64 * 16; idx += 256) {
                int r = idx >> 4, kq = idx & 15;
                int rr = min(row0 + r, N_NODES - 1);
                *(float4*)&Xs[r][kq * 4] = *(const float4*)&X[rr * C_IN + k0 + kq * 4];
            }
            #pragma unroll
            for (int idx = tid; idx < 64 * 16; idx += 256) {
                int kk = idx >> 4, cq = idx & 15;
                *(float4*)&Ws[kk][cq * 4] = *(const float4*)&W1[(k0 + kk) * C + cq * 4];
            }
            __syncthreads();
            gemm_core(Xs, Ws, acc2, rg, cg);
            __syncthreads();
        }
        #pragma unroll
        for (int j = 0; j < 4; j++) {
            int r = row0 + rg * 4 + j;
            if (r >= N_NODES) continue;
            float2 p0 = upk2(acc2[j][0]);
            float2 p1 = upk2(acc2[j][1]);
            __half2 h0 = __floats2half2_rn(p0.x, p0.y);
            __half2 h1 = __floats2half2_rn(p1.x, p1.y);
            uint2 u;
            u.x = *(const unsigned int*)&h0;
            u.y = *(const unsigned int*)&h1;
            *(uint2*)&g_bufA0[r * 32 + cg * 2] = u;
        }
    } else {
        float* w3row = smem;                 // [256]
        float (*part)[C] = (float(*)[C])(smem + HID3);
        int bid = blockIdx.x - EDGE_BLK - GEMM1_BLK;   // 0..64
        int c  = tid & 63;
        int jq = tid >> 6;                   // 0..3
        if (bid < 64) {
            w3row[tid] = W3[bid * HID3 + tid];
            __syncthreads();
            float acc = 0.0f;
            #pragma unroll 8
            for (int jj = 0; jj < 64; jj++) {
                int j = jq * 64 + jj;
                acc = fmaf(w3row[j], W4[j * C + c], acc);
            }
            part[jq][c] = acc;
            __syncthreads();
            if (jq == 0)
                g_Wc[bid * C + c] = (part[0][c] + part[1][c]) + (part[2][c] + part[3][c]);
        } else {
            float acc = 0.0f;
            #pragma unroll 8
            for (int jj = 0; jj < 64; jj++) {
                int j = jq * 64 + jj;
                acc = fmaf(b3[j], W4[j * C + c], acc);
            }
            part[jq][c] = acc;
            __syncthreads();
            if (jq == 0)
                g_bc[c] = (part[0][c] + part[1][c]) + (part[2][c] + part[3][c]) + b4[c];
        }
    }
}

// ---------------- 3-phase exclusive scan (R14-proven) -----------------------
__global__ void k_scan1() {
    __shared__ int sh[SCAN_B];
    int t = threadIdx.x;
    int i = blockIdx.x * SCAN_B + t;
    int v = (i < N_NODES) ? g_deg[i] : 0;
    if (i < N_NODES) g_dinv[i] = rsqrtf((float)v + 1.0f);
    sh[t] = v;
    __syncthreads();
    for (int off = 1; off < SCAN_B; off <<= 1) {
        int add = (t >= off) ? sh[t - off] : 0;
        __syncthreads();
        sh[t] += add;
        __syncthreads();
    }
    if (i < N_NODES) g_rowptr[i] = sh[t] - v;
    if (t == SCAN_B - 1) g_blocksums[blockIdx.x] = sh[t];
}

__global__ void k_scan2() {
    __shared__ int sh[SCAN_B];
    int t = threadIdx.x;
    int v = (t < SCAN_NB) ? g_blocksums[t] : 0;
    sh[t] = v;
    __syncthreads();
    for (int off = 1; off < SCAN_B; off <<= 1) {
        int add = (t >= off) ? sh[t - off] : 0;
        __syncthreads();
        sh[t] += add;
        __syncthreads();
    }
    if (t < SCAN_NB) g_blocksums[t] = sh[t] - v;
}

__global__ void k_scan3() {
    int i = blockIdx.x * SCAN_B + threadIdx.x;
    if (i < N_NODES) {
        int r = g_rowptr[i] + g_blocksums[blockIdx.x];
        g_rowptr[i]   = r;
        g_writepos[i] = r;
    }
    if (i == 0) g_rowptr[N_NODES] = N_EDGES;
}

__global__ void k_fill(const void* __restrict__ ei) {
    int e = blockIdx.x * blockDim.x + threadIdx.x;
    if (e >= N_EDGES) return;
    int s, d;
    if (g_is64) {
        const long long* p = (const long long*)ei;
        s = (int)p[e];
        d = (int)p[N_EDGES + e];
    } else {
        const int* p = (const int*)ei;
        s = p[e];
        d = p[N_EDGES + e];
    }
    if ((unsigned)s >= N_NODES || (unsigned)d >= N_NODES) { s = 0; d = 0; }
    int p2 = atomicAdd(&g_writepos[d], 1);
    g_colsrc[p2] = s;
}

// ---------------- CSR aggregation -------------------------------------------
// SCALED=0 (layer1): H=bufA0 holds h UNscaled -> multiply dinv[s] per edge.
// SCALED=1 (layer2): H=bufA1 holds h*dinv     -> plain sum.
// out: bufB = relu(dinv[i]*(sum + self) + bias)
template <int SCALED>
__global__ void k_agg(const float* __restrict__ bias) {
    int warp = (blockIdx.x * blockDim.x + threadIdx.x) >> 5;
    int lane = threadIdx.x & 31;
    if (warp >= N_NODES) return;

    const __half2* H = SCALED ? g_bufA1 : g_bufA0;
    float di = g_dinv[warp];
    float2 self = __half22float2(H[warp * 32 + lane]);
    float2 acc;
    if (SCALED) { acc = self; }
    else        { acc.x = self.x * di; acc.y = self.y * di; }

    int beg = g_rowptr[warp];
    int end = g_rowptr[warp + 1];
    int e = beg;
    for (; e + 4 <= end; e += 4) {
        int s0 = g_colsrc[e + 0];
        int s1 = g_colsrc[e + 1];
        int s2 = g_colsrc[e + 2];
        int s3 = g_colsrc[e + 3];
        float2 v0 = __half22float2(H[s0 * 32 + lane]);
        float2 v1 = __half22float2(H[s1 * 32 + lane]);
        float2 v2 = __half22float2(H[s2 * 32 + lane]);
        float2 v3 = __half22float2(H[s3 * 32 + lane]);
        if (SCALED) {
            acc.x += (v0.x + v1.x) + (v2.x + v3.x);
            acc.y += (v0.y + v1.y) + (v2.y + v3.y);
        } else {
            float d0 = g_dinv[s0], d1 = g_dinv[s1], d2 = g_dinv[s2], d3 = g_dinv[s3];
            acc.x = fmaf(v0.x, d0, acc.x); acc.y = fmaf(v0.y, d0, acc.y);
            acc.x = fmaf(v1.x, d1, acc.x); acc.y = fmaf(v1.y, d1, acc.y);
            acc.x = fmaf(v2.x, d2, acc.x); acc.y = fmaf(v2.y, d2, acc.y);
            acc.x = fmaf(v3.x, d3, acc.x); acc.y = fmaf(v3.y, d3, acc.y);
        }
    }
    for (; e < end; e++) {
        int s = g_colsrc[e];
        float2 v = __half22float2(H[s * 32 + lane]);
        if (SCALED) { acc.x += v.x; acc.y += v.y; }
        else {
            float ds = g_dinv[s];
            acc.x = fmaf(v.x, ds, acc.x);
            acc.y = fmaf(v.y, ds, acc.y);
        }
    }
    float2 b = ((const float2*)bias)[lane];
    float2 o;
    o.x = fmaxf(fmaf(acc.x, di, b.x), 0.0f);
    o.y = fmaxf(fmaf(acc.y, di, b.y), 0.0f);
    ((float2*)g_bufB)[warp * 32 + lane] = o;
}

// ---------------- GEMM on bufB (K=64): layer2 / output ----------------------
// MODE 1: W=W2   -> bufA1 = fp16(acc * dinv)
// MODE 2: W=g_Wc -> acc + bc, fused log_softmax -> Out
template <int MODE>
__global__ void k_gemm(const float* __restrict__ Wext, float* __restrict__ Out) {
    __shared__ float Xs[32][64];
    __shared__ float Ws[64][64];
    const float* W = (MODE == 2) ? g_Wc : Wext;

    int tid = threadIdx.x;          // 128 threads
    int cg  = tid & 15;
    int rg  = tid >> 4;
    int row0 = blockIdx.x * 32;

    unsigned long long acc2[4][2] = {};

    #pragma unroll
    for (int idx = tid; idx < 32 * 16; idx += 128) {
        int r = idx >> 4, kq = idx & 15;
        *(float4*)&Xs[r][kq * 4] = *(const float4*)&g_bufB[(row0 + r) * C + kq * 4];
    }
    #pragma unroll
    for (int idx = tid; idx < 64 * 16; idx += 128) {
        int kk = idx >> 4, cq = idx & 15;
        *(float4*)&Ws[kk][cq * 4] = *(const float4*)&W[kk * C + cq * 4];
    }
    __syncthreads();
    gemm_core(Xs, Ws, acc2, rg, cg);

    if (MODE == 1) {
        #pragma unroll
        for (int j = 0; j < 4; j++) {
            int r = row0 + rg * 4 + j;
            float s = g_dinv[r];
            float2 p0 = upk2(acc2[j][0]);
            float2 p1 = upk2(acc2[j][1]);
            __half2 h0 = __floats2half2_rn(p0.x * s, p0.y * s);
            __half2 h1 = __floats2half2_rn(p1.x * s, p1.y * s);
            uint2 u;
            u.x = *(const unsigned int*)&h0;
            u.y = *(const unsigned int*)&h1;
            *(uint2*)&g_bufA1[r * 32 + cg * 2] = u;
        }
    } else {
        __syncthreads();
        #pragma unroll
        for (int j = 0; j < 4; j++) {
            float2 p0 = upk2(acc2[j][0]);
            float2 p1 = upk2(acc2[j][1]);
            float4 o;
            o.x = p0.x + g_bc[cg * 4 + 0];
            o.y = p0.y + g_bc[cg * 4 + 1];
            o.z = p1.x + g_bc[cg * 4 + 2];
            o.w = p1.y + g_bc[cg * 4 + 3];
            *(float4*)&Xs[rg * 4 + j][cg * 4] = o;
        }
        __syncthreads();
        int wid  = tid >> 5;
        int lane = tid & 31;
        #pragma unroll
        for (int j = 0; j < 8; j++) {
            int r = wid * 8 + j;
            float2 y = ((const float2*)&Xs[r][0])[lane];
            float m = fmaxf(y.x, y.y);
            #pragma unroll
            for (int off = 16; off; off >>= 1)
                m = fmaxf(m, __shfl_xor_sync(0xffffffffu, m, off));
            float se = expf(y.x - m) + expf(y.y - m);
            #pragma unroll
            for (int off = 16; off; off >>= 1)
                se += __shfl_xor_sync(0xffffffffu, se, off);
            float lse = m + logf(se);
            float2 o;
            o.x = y.x - lse;
            o.y = y.y - lse;
            ((float2*)&Out[(row0 + r) * C])[lane] = o;
        }
    }
}

// ---------------- launch ----------------------------------------------------
extern "C" void kernel_launch(void* const* d_in, const int* in_sizes, int n_in,
                              void* d_out, int out_size) {
    const float* x  = (const float*)d_in[0];
    const void*  ei = d_in[1];
    const float* W1 = (const float*)d_in[2];
    const float* b1 = (const float*)d_in[3];
    const float* W2 = (const float*)d_in[4];
    const float* b2 = (const float*)d_in[5];
    const float* W3 = (const float*)d_in[6];
    const float* b3 = (const float*)d_in[7];
    const float* W4 = (const float*)d_in[8];
    const float* b4 = (const float*)d_in[9];
    float* out = (float*)d_out;

    const int NODE_BLK = (N_NODES + 255) / 256;
    const int WARP_BLK = (N_NODES * 32 + 255) / 256;
    const int GEMM_BLK = N_NODES / 32;   // 3125, exact

    k_zero_probe<<<NODE_BLK, 256>>>((const int*)ei);
    // histogram + GEMM1 + Wc fold, co-scheduled
    k_fat<<<EDGE_BLK + GEMM1_BLK + 65, 256>>>(ei, x, W1, W3, W4, b3, b4);
    k_scan1<<<SCAN_NB, SCAN_B>>>();
    k_scan2<<<1, SCAN_B>>>();
    k_scan3<<<SCAN_NB, SCAN_B>>>();
    k_fill<<<EDGE_BLK, 256>>>(ei);

    // Layer 1 agg (applies dinv[s] per edge), then layer2 GEMM
    k_agg<0><<<WARP_BLK, 256>>>(b1);
    k_gemm<1><<<GEMM_BLK, 128>>>(W2, nullptr);

    // Layer 2 agg, then folded linear + log_softmax
    k_agg<1><<<WARP_BLK, 256>>>(b2);
    k_gemm<2><<<GEMM_BLK, 128>>>(nullptr, out);
}